// round 2
// baseline (speedup 1.0000x reference)
#include <cuda_runtime.h>
#include <cuda_bf16.h>

// DrugBAN fused kernel for GB300/B200.
//
// Algebraic simplification: softmax rows sum to exactly 1, so
//   drug_ctx[b,:] = (1/NT) * sum_{nodes i in graph b, rank<NMAX} drug_x[i,:]
//   tgt_ctx[b,:]  = (1/NT) * sum_t target_h[b,t,:]
// W_a and the attention GEMM/softmax cancel out entirely.
//
// Inputs (metadata order):
//   d_in[0] drug_x    float32 [16384, 256]
//   d_in[1] batch_idx int32   [16384]   (sorted)
//   d_in[2] target_h  float32 [64, 1024, 256]
//   d_in[3] W_a       float32 [256, 256]  (mathematically unused)
// Output: float32 [64, 512]  (drug_ctx | tgt_ctx)

#define NT_LEN   1024
#define D_DIM    256
#define NMAX_CAP 512
#define BATCH_B  64

__device__ __forceinline__ int lb_search(const int* __restrict__ a, int n, int key) {
    int lo = 0, hi = n;
    while (lo < hi) {
        int mid = (lo + hi) >> 1;
        if (__ldg(a + mid) < key) lo = mid + 1; else hi = mid;
    }
    return lo;
}

__global__ __launch_bounds__(256, 8)
void drugban_fused_kernel(const float* __restrict__ drug_x,
                          const int*   __restrict__ batch_idx,
                          const float* __restrict__ target_h,
                          float*       __restrict__ out,
                          int n_nodes) {
    const int b    = blockIdx.x;     // batch index 0..63
    const int part = blockIdx.y;     // 0..3 drug quarters, 4..7 target quarters
    const int tid  = threadIdx.x;    // 256 threads
    const int col  = tid & 15;       // float4 column within the 64-dim slice
    const int row  = tid >> 4;       // 0..15 row group

    float4 acc = make_float4(0.f, 0.f, 0.f, 0.f);

    if (part < 4) {
        // ---- drug segment sum, dims [part*64, part*64+64) ----
        // batch_idx is sorted: binary search the node range of graph b.
        // (uniform across threads; cheap L1/L2-resident searches)
        int start = lb_search(batch_idx, n_nodes, b);
        int end   = lb_search(batch_idx, n_nodes, b + 1);
        if (end - start > NMAX_CAP) end = start + NMAX_CAP;  // pos>=NMAX dropped

        // row stride in float4 units: 256 floats = 64 float4
        const float4* base = reinterpret_cast<const float4*>(drug_x)
                             + (size_t)part * 16 + col;
        int i = start + row;
        // unroll-by-2 manually for MLP without overrunning
        for (; i + 16 < end; i += 32) {
            float4 v0 = base[(size_t)i * 64];
            float4 v1 = base[(size_t)(i + 16) * 64];
            acc.x += v0.x + v1.x; acc.y += v0.y + v1.y;
            acc.z += v0.z + v1.z; acc.w += v0.w + v1.w;
        }
        if (i < end) {
            float4 v = base[(size_t)i * 64];
            acc.x += v.x; acc.y += v.y; acc.z += v.z; acc.w += v.w;
        }
    } else {
        // ---- target mean, dims [(part-4)*64, (part-4)*64+64) ----
        const int q = part - 4;
        const float4* base = reinterpret_cast<const float4*>(target_h)
                             + (size_t)b * (NT_LEN * 64) + (size_t)q * 16 + col;
        #pragma unroll 4
        for (int t = row; t < NT_LEN; t += 16) {
            float4 v = base[(size_t)t * 64];
            acc.x += v.x; acc.y += v.y; acc.z += v.z; acc.w += v.w;
        }
    }

    // ---- tree-reduce the 16 row groups (stride-16 layout keeps col fixed) ----
    __shared__ float4 red[256];
    red[tid] = acc;
    __syncthreads();
    #pragma unroll
    for (int s = 128; s >= 16; s >>= 1) {
        if (tid < s) {
            float4 o = red[tid + s];
            float4 m = red[tid];
            m.x += o.x; m.y += o.y; m.z += o.z; m.w += o.w;
            red[tid] = m;
        }
        __syncthreads();
    }

    if (tid < 16) {
        const float scale = 1.0f / (float)NT_LEN;  // both halves divide by NT
        float4 r = red[tid];
        r.x *= scale; r.y *= scale; r.z *= scale; r.w *= scale;
        // out layout: [b, 512] = [drug_ctx(256) | tgt_ctx(256)]
        int off = b * 512 + ((part < 4) ? part * 64 : 256 + (part - 4) * 64);
        reinterpret_cast<float4*>(out + off)[tid] = r;
    }
}

extern "C" void kernel_launch(void* const* d_in, const int* in_sizes, int n_in,
                              void* d_out, int out_size) {
    const float* drug_x    = (const float*)d_in[0];
    const int*   batch_idx = (const int*)d_in[1];
    const float* target_h  = (const float*)d_in[2];
    // d_in[3] (W_a) cancels out mathematically; unused.
    float* out = (float*)d_out;
    int n_nodes = in_sizes[1];

    dim3 grid(BATCH_B, 8);
    drugban_fused_kernel<<<grid, 256>>>(drug_x, batch_idx, target_h, out, n_nodes);
}